// round 7
// baseline (speedup 1.0000x reference)
#include <cuda_runtime.h>
#include <stdint.h>

// Dataset-fixed shapes. Harness delivers uint8 arrays EXPANDED to one value
// 0..255 per 32-bit element (int32 or float32 — uniform-detected at runtime).
//   weights: 524288 elems, flip: 16777216 elems (32 layers x 524288)
//   out: 524289 f32 = new_weights byte values ++ update_ratio  [or 524288 i32]
#define WORDS       131072            // packed uint32 words
#define LAYERS      32
#define TOTAL_BITS  4194304
#define LAYER_U4    131072            // uint4 per layer
#define FLIP_ELEMS  16777216
#define W_ELEMS     524288
#define NBLK        592               // 4 * 148 SMs: every SM gets EXACTLY 4 blocks
#define NTHR        256

// Monotonic counters (graph-replay-safe: each run adds exactly NBLK; target is
// the next multiple of NBLK). Zero-initialized at module load.
__device__ unsigned int g_arrive = 0;
__device__ unsigned int g_done   = 0;
__device__ unsigned int g_cnt_part[NBLK];
__device__ unsigned int g_mask_part[NBLK];

// Full adder on bit-planes: h = majority (carry), l = xor (sum). 2 LOP3s.
__device__ __forceinline__ void CSA(uint32_t& h, uint32_t& l,
                                    uint32_t a, uint32_t b, uint32_t c) {
    uint32_t u = a ^ b;
    h = (a & b) | (u & c);
    l = u ^ c;
}

// 4 expanded elements -> one packed byte word (elem k -> byte k)
__device__ __forceinline__ uint32_t pack4i(uint4 v) {   // int32-expanded path
    return __byte_perm(__byte_perm(v.x, v.y, 0x0040),
                       __byte_perm(v.z, v.w, 0x0040), 0x5410);
}
__device__ __forceinline__ uint32_t pack4f(uint4 v) {   // float32-expanded path
    uint32_t b0 = (uint32_t)__uint_as_float(v.x), b1 = (uint32_t)__uint_as_float(v.y);
    uint32_t b2 = (uint32_t)__uint_as_float(v.z), b3 = (uint32_t)__uint_as_float(v.w);
    return __byte_perm(__byte_perm(b0, b1, 0x0040),
                       __byte_perm(b2, b3, 0x0040), 0x5410);
}

// Compress 8 packed words into bit-sliced (ones,twos,fours,eights). ~14 LOP3.
__device__ __forceinline__ void compress8(const uint32_t* p, uint32_t& ones,
                                          uint32_t& twos, uint32_t& fours,
                                          uint32_t& eights) {
    uint32_t c1, c2, c3, x1, x2, x3;
    CSA(c1, x1, p[0], p[1], p[2]);
    CSA(c2, x2, x1,   p[3], p[4]);
    CSA(c3, x3, x2,   p[5], p[6]);
    ones = x3 ^ p[7];
    uint32_t c4 = x3 & p[7];
    uint32_t d1, tt;
    CSA(d1, tt, c1, c2, c3);
    twos = tt ^ c4;
    uint32_t d2 = tt & c4;
    fours  = d1 ^ d2;
    eights = d1 & d2;
}

__global__ void __launch_bounds__(NTHR, 4) k_fused(
    const uint4* __restrict__ flip4,
    const uint4* __restrict__ weights4,
    const float* __restrict__ vpm,
    float* __restrict__ outf,
    int*  __restrict__ outi,
    int as_float)
{
    __shared__ unsigned int red[8];
    __shared__ unsigned int sh;

    const int tid  = threadIdx.x;
    const int warp = tid >> 5;
    const int lane = tid & 31;

    // Balanced word range for this block: 221 or 222 words, so every block
    // (and thus every SM, at exactly 4 blocks/SM) does near-identical work.
    const int wbeg = (int)(((unsigned long long)blockIdx.x       * WORDS) / NBLK);
    const int wend = (int)(((unsigned long long)(blockIdx.x + 1) * WORDS) / NBLK);
    const bool has = (wbeg + tid) < wend;
    const int  w   = has ? (wbeg + tid) : wbeg;     // safe dummy index when idle

    // Uniform dtype detect: int32 values 0..255 never set bits >= 9; float32
    // encodings of values >= 1.0 do. OR of 8 elements -> P(miss) ~ (1/256)^8.
    if (tid == 0) {
        const uint32_t* r = (const uint32_t*)flip4;
        uint32_t o = r[0] | r[1] | r[2] | r[3] | r[4] | r[5] | r[6] | r[7];
        sh = (o >> 9) ? 1u : 0u;
    }
    __syncthreads();
    const bool isf = (sh != 0);
    __syncthreads();                               // sh reused later

    // ---- Phase 1: bit-sliced popcount of 32 layers (registers only) ----
    uint32_t s[6] = {0, 0, 0, 0, 0, 0};            // planes: bit k of each count
    if (has) {
        #pragma unroll
        for (int ch = 0; ch < 4; ch++) {
            uint4 v[8];
            #pragma unroll
            for (int j = 0; j < 8; j++)            // 8 LDG.128 front-batched
                v[j] = flip4[(size_t)(ch * 8 + j) * LAYER_U4 + w];
            uint32_t p[8];
            if (isf) {
                #pragma unroll
                for (int j = 0; j < 8; j++) p[j] = pack4f(v[j]);
            } else {
                #pragma unroll
                for (int j = 0; j < 8; j++) p[j] = pack4i(v[j]);
            }
            uint32_t o1, t2, f4, e8;
            compress8(p, o1, t2, f4, e8);
            // ripple-add (o1,t2,f4,e8) into planes s[0..5]
            uint32_t c  = s[0] & o1;  s[0] ^= o1;                // weight 1
            uint32_t c2; CSA(c2, s[1], s[1], c,  t2);            // weight 2
            uint32_t c3; CSA(c3, s[2], s[2], c2, f4);            // weight 4
            uint32_t c4; CSA(c4, s[3], s[3], c3, e8);            // weight 8
            uint32_t c5 = s[4] & c4;  s[4] ^= c4;                // weight 16
            s[5] ^= c5;                                          // weight 32
        }
    }

    // Prefetch weights (overlaps the barrier wait)
    const uint4 wv = has ? weights4[w] : make_uint4(0, 0, 0, 0);

    // This thread's vote total: sum_k 2^k * popc(s_k)  (idle threads: 0)
    unsigned lanesum = __popc(s[0]) + 2 * __popc(s[1]) + 4 * __popc(s[2])
                     + 8 * __popc(s[3]) + 16 * __popc(s[4]) + 32 * __popc(s[5]);
    #pragma unroll
    for (int k = 16; k; k >>= 1) lanesum += __shfl_xor_sync(0xFFFFFFFFu, lanesum, k);
    if (lane == 0) red[warp] = lanesum;
    __syncthreads();

    // ---- Grid barrier (replay-safe monotonic counter) ----
    if (tid == 0) {
        unsigned b = 0;
        #pragma unroll
        for (int i = 0; i < 8; i++) b += red[i];
        g_cnt_part[blockIdx.x] = b;
        __threadfence();
        const unsigned old = atomicAdd(&g_arrive, 1u);
        const unsigned target = (old / NBLK) * NBLK + NBLK;
        while (*(volatile unsigned int*)&g_arrive < target) __nanosleep(64);
        __threadfence();
    }
    __syncthreads();

    // ---- Global total -> threshold ----
    {
        unsigned t = 0;
        for (int i = tid; i < NBLK; i += NTHR) t += g_cnt_part[i];
        #pragma unroll
        for (int k = 16; k; k >>= 1) t += __shfl_xor_sync(0xFFFFFFFFu, t, k);
        if (lane == 0) red[warp] = t;
        __syncthreads();
        if (tid == 0) {
            unsigned tt = 0;
            #pragma unroll
            for (int i = 0; i < 8; i++) tt += red[i];
            sh = tt;
        }
        __syncthreads();
    }
    const unsigned total = sh;
    // p = max(vote_p_max, mean/32); mask = votes > p*32; integer votes:
    //   votes > th <=> votes > floor(th)
    const float mean = (float)((double)total * (1.0 / (double)TOTAL_BITS));
    const float p    = fmaxf(vpm[0], mean * (1.0f / 32.0f));
    const unsigned tb = (unsigned)floorf(p * 32.0f);

    // ---- Bit-sliced compare count > tb : result IS the packed mask word ----
    uint32_t gt = 0, eq = 0xFFFFFFFFu;
    #pragma unroll
    for (int k = 5; k >= 0; k--) {
        const uint32_t tk = (uint32_t)(-(int)((tb >> k) & 1u));  // plane of tb bit
        gt |= eq & s[k] & ~tk;
        eq &= ~(s[k] ^ tk);
    }
    const uint32_t mask = has ? gt : 0u;

    if (has) {
        const uint32_t wword = isf ? pack4f(wv) : pack4i(wv);
        const uint32_t xw    = ~(mask ^ wword);    // bytewise XNOR
        if (as_float) {
            float4 o = { (float)( xw        & 0xFFu), (float)((xw >> 8)  & 0xFFu),
                         (float)((xw >> 16) & 0xFFu), (float)((xw >> 24) & 0xFFu) };
            ((float4*)outf)[w] = o;
        } else {
            int4 o = { (int)( xw        & 0xFFu), (int)((xw >> 8)  & 0xFFu),
                       (int)((xw >> 16) & 0xFFu), (int)((xw >> 24) & 0xFFu) };
            ((int4*)outi)[w] = o;
        }
    }

    // ---- Mask popcount partials; last finisher writes the ratio ----
    unsigned mp = __popc(mask);
    #pragma unroll
    for (int k = 16; k; k >>= 1) mp += __shfl_xor_sync(0xFFFFFFFFu, mp, k);
    if (lane == 0) red[warp] = mp;
    __syncthreads();
    if (tid == 0) {
        unsigned b = 0;
        #pragma unroll
        for (int i = 0; i < 8; i++) b += red[i];
        g_mask_part[blockIdx.x] = b;
        __threadfence();
        const unsigned old = atomicAdd(&g_done, 1u);
        sh = ((old % NBLK) == NBLK - 1) ? 1u : 0u;
    }
    __syncthreads();
    if (sh) {
        __threadfence();
        unsigned t = 0;
        for (int i = tid; i < NBLK; i += NTHR) t += g_mask_part[i];
        #pragma unroll
        for (int k = 16; k; k >>= 1) t += __shfl_xor_sync(0xFFFFFFFFu, t, k);
        if (lane == 0) red[warp] = t;
        __syncthreads();
        if (tid == 0 && as_float) {
            unsigned tt = 0;
            #pragma unroll
            for (int i = 0; i < 8; i++) tt += red[i];
            outf[W_ELEMS] = (float)((double)tt * (1.0 / (double)TOTAL_BITS));
        }
    }
}

extern "C" void kernel_launch(void* const* d_in, const int* in_sizes, int n_in,
                              void* d_out, int out_size)
{
    // Bind by element count (expansion preserves counts).
    const uint4* weights4 = 0;
    const uint4* flip4    = 0;
    const float* vpm      = 0;
    for (int i = 0; i < n_in; i++) {
        if      (in_sizes[i] == FLIP_ELEMS) flip4    = (const uint4*)d_in[i];
        else if (in_sizes[i] == W_ELEMS)    weights4 = (const uint4*)d_in[i];
        else if (in_sizes[i] == 1)          vpm      = (const float*)d_in[i];
    }
    if (!weights4 || !flip4) {
        weights4 = (const uint4*)d_in[0];
        flip4    = (const uint4*)d_in[1];
        vpm      = (const float*)d_in[n_in - 1];
    }

    const int as_float = (out_size != W_ELEMS) ? 1 : 0;

    k_fused<<<NBLK, NTHR>>>(flip4, weights4, vpm,
                            (float*)d_out, (int*)d_out, as_float);
}

// round 8
// speedup vs baseline: 1.1379x; 1.1379x over previous
#include <cuda_runtime.h>
#include <stdint.h>

// Dataset-fixed shapes. Harness delivers uint8 arrays EXPANDED to one value
// 0..255 per 32-bit element (int32 or float32 — uniform-detected at runtime).
//   weights: 524288 elems, flip: 16777216 elems (32 layers x 524288)
//   out: 524289 f32 = new_weights byte values ++ update_ratio  [or 524288 i32]
#define WORDS       131072            // packed uint32 words
#define LAYERS      32
#define TOTAL_BITS  4194304
#define LAYER_U4    131072            // uint4 per layer
#define FLIP_ELEMS  16777216
#define W_ELEMS     524288
#define NBLK        512               // exact fit: 512*256 threads = 131072 words
#define NTHR        256
#define NSTAGE      8                 // 8 stages x 4 layers = 32 layers

// Monotonic counters (graph-replay-safe: each run adds exactly NBLK; target is
// the next multiple of NBLK). Zero-initialized at module load.
__device__ unsigned int g_arrive = 0;
__device__ unsigned int g_done   = 0;
__device__ unsigned int g_cnt_part[NBLK];
__device__ unsigned int g_mask_part[NBLK];

// ---- cp.async helpers (16B, L1-bypass streaming) ----
__device__ __forceinline__ void cpa16(void* sptr, const void* gptr) {
    uint32_t sa = (uint32_t)__cvta_generic_to_shared(sptr);
    asm volatile("cp.async.cg.shared.global [%0], [%1], 16;" :: "r"(sa), "l"(gptr) : "memory");
}
#define CPA_COMMIT() asm volatile("cp.async.commit_group;" ::: "memory")
#define CPA_WAIT(n)  asm volatile("cp.async.wait_group %0;" :: "n"(n) : "memory")

// 4 expanded elements -> one packed byte word (elem k -> byte k)
__device__ __forceinline__ uint32_t pack4i(uint4 v) {   // int32-expanded path
    return __byte_perm(__byte_perm(v.x, v.y, 0x0040),
                       __byte_perm(v.z, v.w, 0x0040), 0x5410);
}
__device__ __forceinline__ uint32_t pack4f(uint4 v) {   // float32-expanded path
    uint32_t b0 = (uint32_t)__uint_as_float(v.x), b1 = (uint32_t)__uint_as_float(v.y);
    uint32_t b2 = (uint32_t)__uint_as_float(v.z), b3 = (uint32_t)__uint_as_float(v.w);
    return __byte_perm(__byte_perm(b0, b1, 0x0040),
                       __byte_perm(b2, b3, 0x0040), 0x5410);
}

// Full adder on bit-planes. 2 LOP3s.
__device__ __forceinline__ void CSA(uint32_t& h, uint32_t& l,
                                    uint32_t a, uint32_t b, uint32_t c) {
    uint32_t u = a ^ b;
    h = (a & b) | (u & c);
    l = u ^ c;
}

// Add 4 packed words into bit-plane accumulators s[0..5]. ~14 LOP3.
__device__ __forceinline__ void acc4(uint32_t* s, uint32_t p0, uint32_t p1,
                                     uint32_t p2, uint32_t p3) {
    uint32_t c1, x1;
    CSA(c1, x1, p0, p1, p2);
    uint32_t ones = x1 ^ p3, c2 = x1 & p3;
    uint32_t twos = c1 ^ c2, fours = c1 & c2;
    uint32_t k1 = s[0] & ones;  s[0] ^= ones;                 // weight 1
    uint32_t k2; CSA(k2, s[1], s[1], k1, twos);               // weight 2
    uint32_t k3; CSA(k3, s[2], s[2], k2, fours);              // weight 4
    uint32_t k4 = s[3] & k3;    s[3] ^= k3;                   // weight 8
    uint32_t k5 = s[4] & k4;    s[4] ^= k4;                   // weight 16
    s[5] ^= k5;                                               // weight 32
}

__global__ void __launch_bounds__(NTHR, 4) k_fused(
    const uint4* __restrict__ flip4,
    const uint4* __restrict__ weights4,
    const float* __restrict__ vpm,
    float* __restrict__ outf,
    int*  __restrict__ outi,
    int as_float)
{
    __shared__ uint4 sbuf[2][4][NTHR];     // 32KB 2-stage ring, 4 layers/stage
    __shared__ unsigned int red[8];
    __shared__ unsigned int sh;

    const int tid  = threadIdx.x;
    const int warp = tid >> 5;
    const int lane = tid & 31;
    const int w    = blockIdx.x * NTHR + tid;   // packed word owned by thread

    // Prologue: stages 0 and 1 in flight before anything else.
    #pragma unroll
    for (int st = 0; st < 2; st++) {
        #pragma unroll
        for (int j = 0; j < 4; j++)
            cpa16(&sbuf[st][j][tid], &flip4[(size_t)(st * 4 + j) * LAYER_U4 + w]);
        CPA_COMMIT();
    }

    // Uniform dtype detect (overlaps prologue latency): int32 values 0..255
    // never set bits >= 9; float32 encodings of values >= 1.0 do.
    if (tid == 0) {
        const uint32_t* r = (const uint32_t*)flip4;
        uint32_t o = r[0] | r[1] | r[2] | r[3] | r[4] | r[5] | r[6] | r[7];
        sh = (o >> 9) ? 1u : 0u;
    }
    __syncthreads();
    const bool isf = (sh != 0);
    __syncthreads();                            // sh reused later

    // ---- Phase 1: pipelined bit-sliced popcount of 32 layers ----
    uint32_t s[6] = {0, 0, 0, 0, 0, 0};
    if (isf) {
        #pragma unroll
        for (int st = 0; st < NSTAGE; st++) {
            if (st < NSTAGE - 1) CPA_WAIT(1); else CPA_WAIT(0);
            const uint4 v0 = sbuf[st & 1][0][tid];
            const uint4 v1 = sbuf[st & 1][1][tid];
            const uint4 v2 = sbuf[st & 1][2][tid];
            const uint4 v3 = sbuf[st & 1][3][tid];
            if (st + 2 < NSTAGE) {              // refill ring (per-thread slots)
                #pragma unroll
                for (int j = 0; j < 4; j++)
                    cpa16(&sbuf[st & 1][j][tid],
                          &flip4[(size_t)((st + 2) * 4 + j) * LAYER_U4 + w]);
                CPA_COMMIT();
            }
            acc4(s, pack4f(v0), pack4f(v1), pack4f(v2), pack4f(v3));
        }
    } else {
        #pragma unroll
        for (int st = 0; st < NSTAGE; st++) {
            if (st < NSTAGE - 1) CPA_WAIT(1); else CPA_WAIT(0);
            const uint4 v0 = sbuf[st & 1][0][tid];
            const uint4 v1 = sbuf[st & 1][1][tid];
            const uint4 v2 = sbuf[st & 1][2][tid];
            const uint4 v3 = sbuf[st & 1][3][tid];
            if (st + 2 < NSTAGE) {
                #pragma unroll
                for (int j = 0; j < 4; j++)
                    cpa16(&sbuf[st & 1][j][tid],
                          &flip4[(size_t)((st + 2) * 4 + j) * LAYER_U4 + w]);
                CPA_COMMIT();
            }
            acc4(s, pack4i(v0), pack4i(v1), pack4i(v2), pack4i(v3));
        }
    }

    // Prefetch weights (overlaps the barrier wait)
    const uint4 wv = weights4[w];

    // This thread's vote total: sum_k 2^k * popc(s_k)
    unsigned lanesum = __popc(s[0]) + 2 * __popc(s[1]) + 4 * __popc(s[2])
                     + 8 * __popc(s[3]) + 16 * __popc(s[4]) + 32 * __popc(s[5]);
    #pragma unroll
    for (int k = 16; k; k >>= 1) lanesum += __shfl_xor_sync(0xFFFFFFFFu, lanesum, k);
    if (lane == 0) red[warp] = lanesum;
    __syncthreads();

    // ---- Grid barrier (replay-safe monotonic counter) ----
    if (tid == 0) {
        unsigned b = 0;
        #pragma unroll
        for (int i = 0; i < 8; i++) b += red[i];
        g_cnt_part[blockIdx.x] = b;
        __threadfence();
        const unsigned old = atomicAdd(&g_arrive, 1u);
        const unsigned target = (old / NBLK) * NBLK + NBLK;
        while (*(volatile unsigned int*)&g_arrive < target) __nanosleep(64);
        __threadfence();
    }
    __syncthreads();

    // ---- Global total -> threshold ----
    {
        unsigned t = 0;
        for (int i = tid; i < NBLK; i += NTHR) t += g_cnt_part[i];
        #pragma unroll
        for (int k = 16; k; k >>= 1) t += __shfl_xor_sync(0xFFFFFFFFu, t, k);
        if (lane == 0) red[warp] = t;
        __syncthreads();
        if (tid == 0) {
            unsigned tt = 0;
            #pragma unroll
            for (int i = 0; i < 8; i++) tt += red[i];
            sh = tt;
        }
        __syncthreads();
    }
    const unsigned total = sh;
    // p = max(vote_p_max, mean/32); mask = votes > p*32; integer votes:
    //   votes > th <=> votes > floor(th)
    const float mean = (float)((double)total * (1.0 / (double)TOTAL_BITS));
    const float p    = fmaxf(vpm[0], mean * (1.0f / 32.0f));
    const unsigned tb = (unsigned)floorf(p * 32.0f);

    // ---- Bit-sliced compare count > tb : result IS the packed mask word ----
    uint32_t gt = 0, eq = 0xFFFFFFFFu;
    #pragma unroll
    for (int k = 5; k >= 0; k--) {
        const uint32_t tk = (uint32_t)(-(int)((tb >> k) & 1u));
        gt |= eq & s[k] & ~tk;
        eq &= ~(s[k] ^ tk);
    }
    const uint32_t mask  = gt;
    const uint32_t wword = isf ? pack4f(wv) : pack4i(wv);
    const uint32_t xw    = ~(mask ^ wword);     // bytewise XNOR

    if (as_float) {
        float4 o = { (float)( xw        & 0xFFu), (float)((xw >> 8)  & 0xFFu),
                     (float)((xw >> 16) & 0xFFu), (float)((xw >> 24) & 0xFFu) };
        ((float4*)outf)[w] = o;
    } else {
        int4 o = { (int)( xw        & 0xFFu), (int)((xw >> 8)  & 0xFFu),
                   (int)((xw >> 16) & 0xFFu), (int)((xw >> 24) & 0xFFu) };
        ((int4*)outi)[w] = o;
    }

    // ---- Mask popcount partials; last finisher writes the ratio ----
    unsigned mp = __popc(mask);
    #pragma unroll
    for (int k = 16; k; k >>= 1) mp += __shfl_xor_sync(0xFFFFFFFFu, mp, k);
    if (lane == 0) red[warp] = mp;
    __syncthreads();
    if (tid == 0) {
        unsigned b = 0;
        #pragma unroll
        for (int i = 0; i < 8; i++) b += red[i];
        g_mask_part[blockIdx.x] = b;
        __threadfence();
        const unsigned old = atomicAdd(&g_done, 1u);
        sh = ((old % NBLK) == NBLK - 1) ? 1u : 0u;
    }
    __syncthreads();
    if (sh) {
        __threadfence();
        unsigned t = 0;
        for (int i = tid; i < NBLK; i += NTHR) t += g_mask_part[i];
        #pragma unroll
        for (int k = 16; k; k >>= 1) t += __shfl_xor_sync(0xFFFFFFFFu, t, k);
        if (lane == 0) red[warp] = t;
        __syncthreads();
        if (tid == 0 && as_float) {
            unsigned tt = 0;
            #pragma unroll
            for (int i = 0; i < 8; i++) tt += red[i];
            outf[W_ELEMS] = (float)((double)tt * (1.0 / (double)TOTAL_BITS));
        }
    }
}

extern "C" void kernel_launch(void* const* d_in, const int* in_sizes, int n_in,
                              void* d_out, int out_size)
{
    // Bind by element count (expansion preserves counts).
    const uint4* weights4 = 0;
    const uint4* flip4    = 0;
    const float* vpm      = 0;
    for (int i = 0; i < n_in; i++) {
        if      (in_sizes[i] == FLIP_ELEMS) flip4    = (const uint4*)d_in[i];
        else if (in_sizes[i] == W_ELEMS)    weights4 = (const uint4*)d_in[i];
        else if (in_sizes[i] == 1)          vpm      = (const float*)d_in[i];
    }
    if (!weights4 || !flip4) {
        weights4 = (const uint4*)d_in[0];
        flip4    = (const uint4*)d_in[1];
        vpm      = (const float*)d_in[n_in - 1];
    }

    const int as_float = (out_size != W_ELEMS) ? 1 : 0;

    k_fused<<<NBLK, NTHR>>>(flip4, weights4, vpm,
                            (float*)d_out, (int*)d_out, as_float);
}